// round 11
// baseline (speedup 1.0000x reference)
#include <cuda_runtime.h>

// SSIM loss: 1 - mean(ssim_map(clip(denoised), clip(clean)))
// Separable 11x11 Gaussian (sigma=1.5), zero padding.
// (32,3,512,512) fp32 x2 -> scalar fp32.
// 4-field basis: conv(s), conv(d), conv(s^2), conv(d^2) with s=a+b, d=a-b
// reconstructs all five SSIM moments -> 20% fewer conv FFMAs + less LDS.

#define IMGW 512
#define IMGH 512
#define TW 32
#define TH 64
#define HALO 5
#define RAWV 74          // TH + 2*HALO
#define RAWH 42          // TW + 2*HALO
#define RS 44            // raw tile row stride (float2 units)
#define HS 33            // hsum row stride (elements)
#define NPIX 25165824.0  // 32*3*512*512
#define GX 16
#define GY 8
#define GZ 96
#define NBLK (GX*GY*GZ)  // 12288
#define NTHR 512

__device__ float g_part[NBLK];
__device__ unsigned int g_count;   // zero-init; last block resets to 0

// dynamic smem layout (bytes):
#define OFF_SD   0
#define OFF_HA   (OFF_SD + RAWV*RS*8)        // float2[RAWV*HS]: (F1h, F2h)
#define OFF_HB   (OFF_HA + RAWV*HS*8)        // float2[RAWV*HS]: (F3h, F4h)
#define SMEM_TOT (OFF_HB + RAWV*HS*8)        // 65120 B

__global__ __launch_bounds__(NTHR, 2) void ssim_main_kernel(
    const float* __restrict__ in1, const float* __restrict__ in2,
    float* __restrict__ out) {

    const float W[11] = {
        0.00102838f, 0.00759876f, 0.03600077f, 0.10936073f, 0.21300554f,
        0.26601172f,
        0.21300554f, 0.10936073f, 0.03600077f, 0.00759876f, 0.00102838f
    };

    extern __shared__ char smem[];
    float2* s_sd = reinterpret_cast<float2*>(smem + OFF_SD);
    float2* s_hA = reinterpret_cast<float2*>(smem + OFF_HA);
    float2* s_hB = reinterpret_cast<float2*>(smem + OFF_HB);
    __shared__ float wsum[16];
    __shared__ int s_islast;
    __shared__ double dsum[16];

    const int tid = threadIdx.x;
    const int plane = blockIdx.z;
    const int row0 = blockIdx.y * TH;
    const int col0 = blockIdx.x * TW;
    const float* p1 = in1 + (size_t)plane * (IMGW * IMGH);
    const float* p2 = in2 + (size_t)plane * (IMGW * IMGH);

    // ---- Load + clip, transform to (s, d) = (a+b, a-b), zero halo pad ----
    for (int idx = tid; idx < RAWV * RAWH; idx += NTHR) {
        int r = idx / RAWH;
        int c = idx - r * RAWH;
        int gr = row0 - HALO + r;
        int gc = col0 - HALO + c;
        float s = 0.0f, d = 0.0f;
        if (gr >= 0 && gr < IMGH && gc >= 0 && gc < IMGW) {
            float a = p1[gr * IMGW + gc];
            float b = p2[gr * IMGW + gc];
            a = fminf(fmaxf(a, 0.0f), 1.0f);
            b = fminf(fmaxf(b, 0.0f), 1.0f);
            s = a + b;
            d = a - b;
        }
        s_sd[r * RS + c] = make_float2(s, d);
    }
    __syncthreads();

    // ---- Horizontal pass: 592 tasks (1 row x 4 output cols), strided ----
    for (int g = tid; g < RAWV * 8; g += NTHR) {
        const int r  = g >> 3;
        const int c0 = (g & 7) << 2;
        const float2* row = s_sd + r * RS + c0;

        float f1[4] = {0.f,0.f,0.f,0.f};
        float f2[4] = {0.f,0.f,0.f,0.f};
        float f3[4] = {0.f,0.f,0.f,0.f};
        float f4[4] = {0.f,0.f,0.f,0.f};

        #pragma unroll
        for (int k = 0; k < 14; k++) {
            float2 sd = row[k];
            float ss = sd.x * sd.x;
            float dd = sd.y * sd.y;
            #pragma unroll
            for (int j = 0; j < 4; j++) {
                const int kk = k - j;
                if (kk >= 0 && kk < 11) {
                    f1[j] = fmaf(W[kk], sd.x, f1[j]);
                    f2[j] = fmaf(W[kk], sd.y, f2[j]);
                    f3[j] = fmaf(W[kk], ss,  f3[j]);
                    f4[j] = fmaf(W[kk], dd,  f4[j]);
                }
            }
        }
        int o = r * HS + c0;
        #pragma unroll
        for (int j = 0; j < 4; j++) {
            s_hA[o + j] = make_float2(f1[j], f2[j]);
            s_hB[o + j] = make_float2(f3[j], f4[j]);
        }
    }
    __syncthreads();

    // ---- Vertical pass + SSIM: each thread = 1 col x 4 output rows ----
    float acc = 0.0f;
    {
        const int c  = tid & 31;
        const int r0 = (tid >> 5) << 2;    // 0..60
        float v1[4] = {0.f,0.f,0.f,0.f};
        float v2[4] = {0.f,0.f,0.f,0.f};
        float v3[4] = {0.f,0.f,0.f,0.f};
        float v4[4] = {0.f,0.f,0.f,0.f};

        #pragma unroll
        for (int k = 0; k < 14; k++) {
            int rr = (r0 + k) * HS + c;
            float2 hA = s_hA[rr];
            float2 hB = s_hB[rr];
            #pragma unroll
            for (int j = 0; j < 4; j++) {
                const int kk = k - j;
                if (kk >= 0 && kk < 11) {
                    v1[j] = fmaf(W[kk], hA.x, v1[j]);
                    v2[j] = fmaf(W[kk], hA.y, v2[j]);
                    v3[j] = fmaf(W[kk], hB.x, v3[j]);
                    v4[j] = fmaf(W[kk], hB.y, v4[j]);
                }
            }
        }
        const float C1 = 1e-4f;   // 0.01^2
        const float C2 = 9e-4f;   // 0.03^2
        #pragma unroll
        for (int j = 0; j < 4; j++) {
            // F1 = mu1+mu2, F2 = mu1-mu2, F3 = E(s^2), F4 = E(d^2)
            float f1s = v1[j] * v1[j];
            float f2s = v2[j] * v2[j];
            float P = 0.5f * (f1s - f2s);      // 2*mu1*mu2
            float Q = 0.5f * (f1s + f2s);      // mu1^2 + mu2^2
            float R = 0.5f * (v3[j] - v4[j]);  // 2*E12
            float S = 0.5f * (v3[j] + v4[j]);  // E11 + E22
            float num = (P + C1) * (R - P + C2);
            float den = (Q + C1) * (S - Q + C2);
            acc += __fdividef(num, den);
        }
    }

    // ---- Block reduction -> per-block partial + last-block final reduce ----
    #pragma unroll
    for (int o = 16; o > 0; o >>= 1)
        acc += __shfl_xor_sync(0xffffffffu, acc, o);
    if ((tid & 31) == 0) wsum[tid >> 5] = acc;
    __syncthreads();
    if (tid == 0) {
        float s = 0.0f;
        #pragma unroll
        for (int i = 0; i < 16; i++) s += wsum[i];
        int bid = blockIdx.x + GX * (blockIdx.y + GY * blockIdx.z);
        g_part[bid] = s;
        __threadfence();
        unsigned int old = atomicAdd(&g_count, 1u);
        s_islast = (old == NBLK - 1) ? 1 : 0;
    }
    __syncthreads();

    if (s_islast) {
        __threadfence();
        const volatile float* vp = g_part;
        double d = 0.0;
        for (int i = tid; i < NBLK; i += NTHR) d += (double)vp[i];
        #pragma unroll
        for (int o = 16; o > 0; o >>= 1)
            d += __shfl_xor_sync(0xffffffffu, d, o);
        if ((tid & 31) == 0) dsum[tid >> 5] = d;
        __syncthreads();
        if (tid == 0) {
            double t = 0.0;
            #pragma unroll
            for (int i = 0; i < 16; i++) t += dsum[i];
            out[0] = (float)(1.0 - t * (1.0 / NPIX));
            g_count = 0;   // reset for next graph replay
        }
    }
}

extern "C" void kernel_launch(void* const* d_in, const int* in_sizes, int n_in,
                              void* d_out, int out_size) {
    const float* denoised = (const float*)d_in[0];
    const float* clean    = (const float*)d_in[1];
    float* out = (float*)d_out;

    cudaFuncSetAttribute(ssim_main_kernel,
                         cudaFuncAttributeMaxDynamicSharedMemorySize, SMEM_TOT);

    dim3 grid(GX, GY, GZ);   // 16 x 8 x 96
    ssim_main_kernel<<<grid, NTHR, SMEM_TOT>>>(denoised, clean, out);
}

// round 12
// speedup vs baseline: 1.1605x; 1.1605x over previous
#include <cuda_runtime.h>

// SSIM loss: 1 - mean(ssim_map(clip(denoised), clip(clean)))
// Separable 11x11 Gaussian (sigma=1.5), zero padding.
// (32,3,512,512) fp32 x2 -> scalar fp32.
// 4-field basis (s=a+b, d=a-b): conv(s), conv(d), conv(s^2), conv(d^2).
// Small 32x32 tiles, 256 thr, 5 blocks/SM for cross-block phase overlap.

#define IMGW 512
#define IMGH 512
#define TW 32
#define TH 32
#define HALO 5
#define RAWV 42          // TH + 2*HALO
#define RAWH 42          // TW + 2*HALO
#define RS 44            // raw tile row stride (float2 units)
#define HS 33            // hsum row stride (elements)
#define NPIX 25165824.0  // 32*3*512*512
#define GX 16
#define GY 16
#define GZ 96
#define NBLK (GX*GY*GZ)  // 24576
#define NTHR 256

__device__ float g_part[NBLK];
__device__ unsigned int g_count;   // zero-init; last block resets to 0

// dynamic smem layout (bytes):
#define OFF_SD   0
#define OFF_HA   (OFF_SD + RAWV*RS*8)        // float2[RAWV*HS]: (F1h, F2h)
#define OFF_HB   (OFF_HA + RAWV*HS*8)        // float2[RAWV*HS]: (F3h, F4h)
#define SMEM_TOT (OFF_HB + RAWV*HS*8)        // 36960 B

__global__ __launch_bounds__(NTHR, 5) void ssim_main_kernel(
    const float* __restrict__ in1, const float* __restrict__ in2,
    float* __restrict__ out) {

    const float W[11] = {
        0.00102838f, 0.00759876f, 0.03600077f, 0.10936073f, 0.21300554f,
        0.26601172f,
        0.21300554f, 0.10936073f, 0.03600077f, 0.00759876f, 0.00102838f
    };

    extern __shared__ char smem[];
    float2* s_sd = reinterpret_cast<float2*>(smem + OFF_SD);
    float2* s_hA = reinterpret_cast<float2*>(smem + OFF_HA);
    float2* s_hB = reinterpret_cast<float2*>(smem + OFF_HB);
    __shared__ float wsum[8];
    __shared__ int s_islast;
    __shared__ double dsum[8];

    const int tid = threadIdx.x;
    const int plane = blockIdx.z;
    const int row0 = blockIdx.y * TH;
    const int col0 = blockIdx.x * TW;
    const float* p1 = in1 + (size_t)plane * (IMGW * IMGH);
    const float* p2 = in2 + (size_t)plane * (IMGW * IMGH);

    // ---- Load + clip, transform to (s, d) = (a+b, a-b), zero halo pad ----
    for (int idx = tid; idx < RAWV * RAWH; idx += NTHR) {
        int r = idx / RAWH;
        int c = idx - r * RAWH;
        int gr = row0 - HALO + r;
        int gc = col0 - HALO + c;
        float s = 0.0f, d = 0.0f;
        if (gr >= 0 && gr < IMGH && gc >= 0 && gc < IMGW) {
            float a = p1[gr * IMGW + gc];
            float b = p2[gr * IMGW + gc];
            a = fminf(fmaxf(a, 0.0f), 1.0f);
            b = fminf(fmaxf(b, 0.0f), 1.0f);
            s = a + b;
            d = a - b;
        }
        s_sd[r * RS + c] = make_float2(s, d);
    }
    __syncthreads();

    // ---- Horizontal pass: 336 tasks (1 row x 4 output cols), strided ----
    for (int g = tid; g < RAWV * 8; g += NTHR) {
        const int r  = g >> 3;
        const int c0 = (g & 7) << 2;
        const float2* row = s_sd + r * RS + c0;

        float f1[4] = {0.f,0.f,0.f,0.f};
        float f2[4] = {0.f,0.f,0.f,0.f};
        float f3[4] = {0.f,0.f,0.f,0.f};
        float f4[4] = {0.f,0.f,0.f,0.f};

        #pragma unroll
        for (int k = 0; k < 14; k++) {
            float2 sd = row[k];
            float ss = sd.x * sd.x;
            float dd = sd.y * sd.y;
            #pragma unroll
            for (int j = 0; j < 4; j++) {
                const int kk = k - j;
                if (kk >= 0 && kk < 11) {
                    f1[j] = fmaf(W[kk], sd.x, f1[j]);
                    f2[j] = fmaf(W[kk], sd.y, f2[j]);
                    f3[j] = fmaf(W[kk], ss,  f3[j]);
                    f4[j] = fmaf(W[kk], dd,  f4[j]);
                }
            }
        }
        int o = r * HS + c0;
        #pragma unroll
        for (int j = 0; j < 4; j++) {
            s_hA[o + j] = make_float2(f1[j], f2[j]);
            s_hB[o + j] = make_float2(f3[j], f4[j]);
        }
    }
    __syncthreads();

    // ---- Vertical pass + SSIM: 256 tasks, exactly 1 per thread ----
    float acc = 0.0f;
    {
        const int c  = tid & 31;
        const int r0 = (tid >> 5) << 2;    // 0..28
        float v1[4] = {0.f,0.f,0.f,0.f};
        float v2[4] = {0.f,0.f,0.f,0.f};
        float v3[4] = {0.f,0.f,0.f,0.f};
        float v4[4] = {0.f,0.f,0.f,0.f};

        #pragma unroll
        for (int k = 0; k < 14; k++) {
            int rr = (r0 + k) * HS + c;
            float2 hA = s_hA[rr];
            float2 hB = s_hB[rr];
            #pragma unroll
            for (int j = 0; j < 4; j++) {
                const int kk = k - j;
                if (kk >= 0 && kk < 11) {
                    v1[j] = fmaf(W[kk], hA.x, v1[j]);
                    v2[j] = fmaf(W[kk], hA.y, v2[j]);
                    v3[j] = fmaf(W[kk], hB.x, v3[j]);
                    v4[j] = fmaf(W[kk], hB.y, v4[j]);
                }
            }
        }
        const float C1 = 1e-4f;   // 0.01^2
        const float C2 = 9e-4f;   // 0.03^2
        #pragma unroll
        for (int j = 0; j < 4; j++) {
            // F1 = mu1+mu2, F2 = mu1-mu2, F3 = E(s^2), F4 = E(d^2)
            float f1s = v1[j] * v1[j];
            float f2s = v2[j] * v2[j];
            float P = 0.5f * (f1s - f2s);      // 2*mu1*mu2
            float Q = 0.5f * (f1s + f2s);      // mu1^2 + mu2^2
            float R = 0.5f * (v3[j] - v4[j]);  // 2*E12
            float S = 0.5f * (v3[j] + v4[j]);  // E11 + E22
            float num = (P + C1) * (R - P + C2);
            float den = (Q + C1) * (S - Q + C2);
            acc += __fdividef(num, den);
        }
    }

    // ---- Block reduction -> per-block partial + last-block final reduce ----
    #pragma unroll
    for (int o = 16; o > 0; o >>= 1)
        acc += __shfl_xor_sync(0xffffffffu, acc, o);
    if ((tid & 31) == 0) wsum[tid >> 5] = acc;
    __syncthreads();
    if (tid == 0) {
        float s = 0.0f;
        #pragma unroll
        for (int i = 0; i < 8; i++) s += wsum[i];
        int bid = blockIdx.x + GX * (blockIdx.y + GY * blockIdx.z);
        g_part[bid] = s;
        __threadfence();
        unsigned int old = atomicAdd(&g_count, 1u);
        s_islast = (old == NBLK - 1) ? 1 : 0;
    }
    __syncthreads();

    if (s_islast) {
        __threadfence();
        const volatile float* vp = g_part;
        double d0 = 0.0, d1 = 0.0, d2 = 0.0, d3 = 0.0;
        for (int i = tid; i < NBLK; i += 4 * NTHR) {
            d0 += (double)vp[i];
            d1 += (double)vp[i + NTHR];
            d2 += (double)vp[i + 2 * NTHR];
            d3 += (double)vp[i + 3 * NTHR];
        }
        double d = (d0 + d1) + (d2 + d3);
        #pragma unroll
        for (int o = 16; o > 0; o >>= 1)
            d += __shfl_xor_sync(0xffffffffu, d, o);
        if ((tid & 31) == 0) dsum[tid >> 5] = d;
        __syncthreads();
        if (tid == 0) {
            double t = 0.0;
            #pragma unroll
            for (int i = 0; i < 8; i++) t += dsum[i];
            out[0] = (float)(1.0 - t * (1.0 / NPIX));
            g_count = 0;   // reset for next graph replay
        }
    }
}

extern "C" void kernel_launch(void* const* d_in, const int* in_sizes, int n_in,
                              void* d_out, int out_size) {
    const float* denoised = (const float*)d_in[0];
    const float* clean    = (const float*)d_in[1];
    float* out = (float*)d_out;

    cudaFuncSetAttribute(ssim_main_kernel,
                         cudaFuncAttributeMaxDynamicSharedMemorySize, SMEM_TOT);

    dim3 grid(GX, GY, GZ);   // 16 x 16 x 96
    ssim_main_kernel<<<grid, NTHR, SMEM_TOT>>>(denoised, clean, out);
}

// round 13
// speedup vs baseline: 1.1988x; 1.0331x over previous
#include <cuda_runtime.h>
#include <cuda_fp16.h>

// SSIM loss: 1 - mean(ssim_map(clip(denoised), clip(clean)))
// Separable 11x11 Gaussian (sigma=1.5), zero padding.
// (32,3,512,512) fp32 x2 -> scalar fp32.
// 4-field basis (s=a+b, d=a-b). Intermediate h-sums stored as packed fp16
// (2x half2 per px = 8B for all 4 fields), fp32 accumulation everywhere.

#define IMGW 512
#define IMGH 512
#define TW 32
#define TH 32
#define HALO 5
#define RAWV 42          // TH + 2*HALO
#define RAWH 42          // TW + 2*HALO
#define RS 44            // raw tile row stride (float2 units)
#define HS 33            // hsum row stride (elements)
#define NPIX 25165824.0  // 32*3*512*512
#define GX 16
#define GY 16
#define GZ 96
#define NBLK (GX*GY*GZ)  // 24576
#define NTHR 256

__device__ float g_part[NBLK];
__device__ unsigned int g_count;   // zero-init; last block resets to 0

// dynamic smem layout (bytes):
#define OFF_SD   0
#define OFF_H    (OFF_SD + RAWV*RS*8)        // uint2[RAWV*HS]: {h2(F1,F2), h2(F3,F4)}
#define SMEM_TOT (OFF_H + RAWV*HS*8)         // 25872 B

__global__ __launch_bounds__(NTHR, 5) void ssim_main_kernel(
    const float* __restrict__ in1, const float* __restrict__ in2,
    float* __restrict__ out) {

    const float W[11] = {
        0.00102838f, 0.00759876f, 0.03600077f, 0.10936073f, 0.21300554f,
        0.26601172f,
        0.21300554f, 0.10936073f, 0.03600077f, 0.00759876f, 0.00102838f
    };

    extern __shared__ char smem[];
    float2* s_sd = reinterpret_cast<float2*>(smem + OFF_SD);
    uint2*  s_h  = reinterpret_cast<uint2*>(smem + OFF_H);
    __shared__ float wsum[8];
    __shared__ int s_islast;
    __shared__ double dsum[8];

    const int tid = threadIdx.x;
    const int plane = blockIdx.z;
    const int row0 = blockIdx.y * TH;
    const int col0 = blockIdx.x * TW;
    const float* p1 = in1 + (size_t)plane * (IMGW * IMGH);
    const float* p2 = in2 + (size_t)plane * (IMGW * IMGH);

    // ---- Load + clip, transform to (s, d) = (a+b, a-b), zero halo pad ----
    for (int idx = tid; idx < RAWV * RAWH; idx += NTHR) {
        int r = idx / RAWH;
        int c = idx - r * RAWH;
        int gr = row0 - HALO + r;
        int gc = col0 - HALO + c;
        float s = 0.0f, d = 0.0f;
        if (gr >= 0 && gr < IMGH && gc >= 0 && gc < IMGW) {
            float a = p1[gr * IMGW + gc];
            float b = p2[gr * IMGW + gc];
            a = fminf(fmaxf(a, 0.0f), 1.0f);
            b = fminf(fmaxf(b, 0.0f), 1.0f);
            s = a + b;
            d = a - b;
        }
        s_sd[r * RS + c] = make_float2(s, d);
    }
    __syncthreads();

    // ---- Horizontal pass: 336 tasks (1 row x 4 output cols), strided ----
    for (int g = tid; g < RAWV * 8; g += NTHR) {
        const int r  = g >> 3;
        const int c0 = (g & 7) << 2;
        const float2* row = s_sd + r * RS + c0;

        float f1[4] = {0.f,0.f,0.f,0.f};
        float f2[4] = {0.f,0.f,0.f,0.f};
        float f3[4] = {0.f,0.f,0.f,0.f};
        float f4[4] = {0.f,0.f,0.f,0.f};

        #pragma unroll
        for (int k = 0; k < 14; k++) {
            float2 sd = row[k];
            float ss = sd.x * sd.x;
            float dd = sd.y * sd.y;
            #pragma unroll
            for (int j = 0; j < 4; j++) {
                const int kk = k - j;
                if (kk >= 0 && kk < 11) {
                    f1[j] = fmaf(W[kk], sd.x, f1[j]);
                    f2[j] = fmaf(W[kk], sd.y, f2[j]);
                    f3[j] = fmaf(W[kk], ss,  f3[j]);
                    f4[j] = fmaf(W[kk], dd,  f4[j]);
                }
            }
        }
        int o = r * HS + c0;
        #pragma unroll
        for (int j = 0; j < 4; j++) {
            __half2 hA = __floats2half2_rn(f1[j], f2[j]);
            __half2 hB = __floats2half2_rn(f3[j], f4[j]);
            uint2 pk;
            pk.x = *reinterpret_cast<unsigned int*>(&hA);
            pk.y = *reinterpret_cast<unsigned int*>(&hB);
            s_h[o + j] = pk;
        }
    }
    __syncthreads();

    // ---- Vertical pass + SSIM: 256 tasks, exactly 1 per thread ----
    float acc = 0.0f;
    {
        const int c  = tid & 31;
        const int r0 = (tid >> 5) << 2;    // 0..28
        float v1[4] = {0.f,0.f,0.f,0.f};
        float v2[4] = {0.f,0.f,0.f,0.f};
        float v3[4] = {0.f,0.f,0.f,0.f};
        float v4[4] = {0.f,0.f,0.f,0.f};

        #pragma unroll
        for (int k = 0; k < 14; k++) {
            int rr = (r0 + k) * HS + c;
            uint2 pk = s_h[rr];
            float2 hA = __half22float2(*reinterpret_cast<__half2*>(&pk.x));
            float2 hB = __half22float2(*reinterpret_cast<__half2*>(&pk.y));
            #pragma unroll
            for (int j = 0; j < 4; j++) {
                const int kk = k - j;
                if (kk >= 0 && kk < 11) {
                    v1[j] = fmaf(W[kk], hA.x, v1[j]);
                    v2[j] = fmaf(W[kk], hA.y, v2[j]);
                    v3[j] = fmaf(W[kk], hB.x, v3[j]);
                    v4[j] = fmaf(W[kk], hB.y, v4[j]);
                }
            }
        }
        const float C1 = 1e-4f;   // 0.01^2
        const float C2 = 9e-4f;   // 0.03^2
        #pragma unroll
        for (int j = 0; j < 4; j++) {
            // F1 = mu1+mu2, F2 = mu1-mu2, F3 = E(s^2), F4 = E(d^2)
            float f1s = v1[j] * v1[j];
            float f2s = v2[j] * v2[j];
            float P = 0.5f * (f1s - f2s);      // 2*mu1*mu2
            float Q = 0.5f * (f1s + f2s);      // mu1^2 + mu2^2
            float R = 0.5f * (v3[j] - v4[j]);  // 2*E12
            float S = 0.5f * (v3[j] + v4[j]);  // E11 + E22
            float num = (P + C1) * (R - P + C2);
            float den = (Q + C1) * (S - Q + C2);
            acc += __fdividef(num, den);
        }
    }

    // ---- Block reduction -> per-block partial + last-block final reduce ----
    #pragma unroll
    for (int o = 16; o > 0; o >>= 1)
        acc += __shfl_xor_sync(0xffffffffu, acc, o);
    if ((tid & 31) == 0) wsum[tid >> 5] = acc;
    __syncthreads();
    if (tid == 0) {
        float s = 0.0f;
        #pragma unroll
        for (int i = 0; i < 8; i++) s += wsum[i];
        int bid = blockIdx.x + GX * (blockIdx.y + GY * blockIdx.z);
        g_part[bid] = s;
        __threadfence();
        unsigned int old = atomicAdd(&g_count, 1u);
        s_islast = (old == NBLK - 1) ? 1 : 0;
    }
    __syncthreads();

    if (s_islast) {
        __threadfence();
        const volatile float* vp = g_part;
        double d0 = 0.0, d1 = 0.0, d2 = 0.0, d3 = 0.0;
        for (int i = tid; i < NBLK; i += 4 * NTHR) {
            d0 += (double)vp[i];
            d1 += (double)vp[i + NTHR];
            d2 += (double)vp[i + 2 * NTHR];
            d3 += (double)vp[i + 3 * NTHR];
        }
        double d = (d0 + d1) + (d2 + d3);
        #pragma unroll
        for (int o = 16; o > 0; o >>= 1)
            d += __shfl_xor_sync(0xffffffffu, d, o);
        if ((tid & 31) == 0) dsum[tid >> 5] = d;
        __syncthreads();
        if (tid == 0) {
            double t = 0.0;
            #pragma unroll
            for (int i = 0; i < 8; i++) t += dsum[i];
            out[0] = (float)(1.0 - t * (1.0 / NPIX));
            g_count = 0;   // reset for next graph replay
        }
    }
}

extern "C" void kernel_launch(void* const* d_in, const int* in_sizes, int n_in,
                              void* d_out, int out_size) {
    const float* denoised = (const float*)d_in[0];
    const float* clean    = (const float*)d_in[1];
    float* out = (float*)d_out;

    cudaFuncSetAttribute(ssim_main_kernel,
                         cudaFuncAttributeMaxDynamicSharedMemorySize, SMEM_TOT);

    dim3 grid(GX, GY, GZ);   // 16 x 16 x 96
    ssim_main_kernel<<<grid, NTHR, SMEM_TOT>>>(denoised, clean, out);
}

// round 15
// speedup vs baseline: 1.2145x; 1.0131x over previous
#include <cuda_runtime.h>
#include <cuda_fp16.h>

// SSIM loss: 1 - mean(ssim_map(clip(denoised), clip(clean)))
// Separable 11x11 Gaussian (sigma=1.5), zero padding.
// (32,3,512,512) fp32 x2 -> scalar fp32.
// 4-field basis (s=a+b, d=a-b); fp16-packed h-sums; packed f32x2 FFMA
// (sm_103a) so each conv tap issues ONE FMA for two fp32 fields.

#define IMGW 512
#define IMGH 512
#define TW 32
#define TH 32
#define HALO 5
#define RAWV 42          // TH + 2*HALO
#define RAWH 42          // TW + 2*HALO
#define RS 44            // raw tile row stride (float2 units)
#define HS 33            // hsum row stride (elements)
#define NPIX 25165824.0  // 32*3*512*512
#define GX 16
#define GY 16
#define GZ 96
#define NBLK (GX*GY*GZ)  // 24576
#define NTHR 256

__device__ float g_part[NBLK];
__device__ unsigned int g_count;   // zero-init; last block resets to 0

typedef unsigned long long u64;

__device__ __forceinline__ u64 pk2(float x, float y) {
    u64 r; asm("mov.b64 %0,{%1,%2};" : "=l"(r) : "f"(x), "f"(y)); return r;
}
__device__ __forceinline__ float2 upk2(u64 v) {
    float2 f; asm("mov.b64 {%0,%1},%2;" : "=f"(f.x), "=f"(f.y) : "l"(v)); return f;
}
__device__ __forceinline__ u64 ffma2(u64 a, u64 b, u64 c) {
    u64 d; asm("fma.rn.f32x2 %0,%1,%2,%3;" : "=l"(d) : "l"(a), "l"(b), "l"(c)); return d;
}
__device__ __forceinline__ u64 fmul2(u64 a, u64 b) {
    u64 d; asm("mul.rn.f32x2 %0,%1,%2;" : "=l"(d) : "l"(a), "l"(b)); return d;
}

// symmetric weight index: W[k] = W[10-k], 6 distinct values
#define WIDX(kk) ((kk) <= 5 ? (kk) : 10 - (kk))

// dynamic smem layout (bytes):
#define OFF_SD   0
#define OFF_H    (OFF_SD + RAWV*RS*8)        // uint2[RAWV*HS]: {h2(F1,F2), h2(F3,F4)}
#define SMEM_TOT (OFF_H + RAWV*HS*8)         // 25872 B

__global__ __launch_bounds__(NTHR, 5) void ssim_main_kernel(
    const float* __restrict__ in1, const float* __restrict__ in2,
    float* __restrict__ out) {

    const float W[6] = {
        0.00102838f, 0.00759876f, 0.03600077f, 0.10936073f, 0.21300554f,
        0.26601172f
    };

    extern __shared__ char smem[];
    float2* s_sd = reinterpret_cast<float2*>(smem + OFF_SD);
    uint2*  s_h  = reinterpret_cast<uint2*>(smem + OFF_H);
    __shared__ float wsum[8];
    __shared__ int s_islast;
    __shared__ double dsum[8];

    const int tid = threadIdx.x;
    const int plane = blockIdx.z;
    const int row0 = blockIdx.y * TH;
    const int col0 = blockIdx.x * TW;
    const float* p1 = in1 + (size_t)plane * (IMGW * IMGH);
    const float* p2 = in2 + (size_t)plane * (IMGW * IMGH);

    // packed weights (6 distinct, both halves equal)
    u64 W2[6];
    #pragma unroll
    for (int i = 0; i < 6; i++) W2[i] = pk2(W[i], W[i]);

    // ---- Load + clip, transform to (s, d) = (a+b, a-b), zero halo pad ----
    for (int idx = tid; idx < RAWV * RAWH; idx += NTHR) {
        int r = idx / RAWH;
        int c = idx - r * RAWH;
        int gr = row0 - HALO + r;
        int gc = col0 - HALO + c;
        float s = 0.0f, d = 0.0f;
        if (gr >= 0 && gr < IMGH && gc >= 0 && gc < IMGW) {
            float a = p1[gr * IMGW + gc];
            float b = p2[gr * IMGW + gc];
            a = fminf(fmaxf(a, 0.0f), 1.0f);
            b = fminf(fmaxf(b, 0.0f), 1.0f);
            s = a + b;
            d = a - b;
        }
        s_sd[r * RS + c] = make_float2(s, d);
    }
    __syncthreads();

    // ---- Horizontal pass: 336 tasks (1 row x 4 output cols), strided ----
    for (int g = tid; g < RAWV * 8; g += NTHR) {
        const int r  = g >> 3;
        const int c0 = (g & 7) << 2;
        const u64* row = reinterpret_cast<const u64*>(s_sd + r * RS + c0);

        u64 am[4] = {0ull,0ull,0ull,0ull};   // (F1,F2)
        u64 aq[4] = {0ull,0ull,0ull,0ull};   // (F3,F4)

        #pragma unroll
        for (int k = 0; k < 14; k++) {
            u64 sdp = row[k];
            u64 sqp = fmul2(sdp, sdp);
            #pragma unroll
            for (int j = 0; j < 4; j++) {
                const int kk = k - j;
                if (kk >= 0 && kk < 11) {
                    am[j] = ffma2(W2[WIDX(kk)], sdp, am[j]);
                    aq[j] = ffma2(W2[WIDX(kk)], sqp, aq[j]);
                }
            }
        }
        int o = r * HS + c0;
        #pragma unroll
        for (int j = 0; j < 4; j++) {
            float2 fm = upk2(am[j]);
            float2 fq = upk2(aq[j]);
            __half2 hA = __floats2half2_rn(fm.x, fm.y);
            __half2 hB = __floats2half2_rn(fq.x, fq.y);
            uint2 pk;
            pk.x = *reinterpret_cast<unsigned int*>(&hA);
            pk.y = *reinterpret_cast<unsigned int*>(&hB);
            s_h[o + j] = pk;
        }
    }
    __syncthreads();

    // ---- Vertical pass + SSIM: 256 tasks, exactly 1 per thread ----
    float acc = 0.0f;
    {
        const int c  = tid & 31;
        const int r0 = (tid >> 5) << 2;    // 0..28
        u64 vA[4] = {0ull,0ull,0ull,0ull};
        u64 vB[4] = {0ull,0ull,0ull,0ull};

        #pragma unroll
        for (int k = 0; k < 14; k++) {
            int rr = (r0 + k) * HS + c;
            uint2 pk = s_h[rr];
            float2 fA = __half22float2(*reinterpret_cast<__half2*>(&pk.x));
            float2 fB = __half22float2(*reinterpret_cast<__half2*>(&pk.y));
            u64 hAp = pk2(fA.x, fA.y);
            u64 hBp = pk2(fB.x, fB.y);
            #pragma unroll
            for (int j = 0; j < 4; j++) {
                const int kk = k - j;
                if (kk >= 0 && kk < 11) {
                    vA[j] = ffma2(W2[WIDX(kk)], hAp, vA[j]);
                    vB[j] = ffma2(W2[WIDX(kk)], hBp, vB[j]);
                }
            }
        }
        const float C1 = 1e-4f;   // 0.01^2
        const float C2 = 9e-4f;   // 0.03^2
        #pragma unroll
        for (int j = 0; j < 4; j++) {
            // vA = (F1, F2) = (mu1+mu2, mu1-mu2); vB = (F3, F4) = (E(s^2), E(d^2))
            u64 sqv = fmul2(vA[j], vA[j]);
            float2 fs = upk2(sqv);
            float2 fB = upk2(vB[j]);
            float P = 0.5f * (fs.x - fs.y);     // 2*mu1*mu2
            float Q = 0.5f * (fs.x + fs.y);     // mu1^2 + mu2^2
            float R = 0.5f * (fB.x - fB.y);     // 2*E12
            float S = 0.5f * (fB.x + fB.y);     // E11 + E22
            float num = (P + C1) * (R - P + C2);
            float den = (Q + C1) * (S - Q + C2);
            acc += __fdividef(num, den);
        }
    }

    // ---- Block reduction -> per-block partial + last-block final reduce ----
    #pragma unroll
    for (int o = 16; o > 0; o >>= 1)
        acc += __shfl_xor_sync(0xffffffffu, acc, o);
    if ((tid & 31) == 0) wsum[tid >> 5] = acc;
    __syncthreads();
    if (tid == 0) {
        float s = 0.0f;
        #pragma unroll
        for (int i = 0; i < 8; i++) s += wsum[i];
        int bid = blockIdx.x + GX * (blockIdx.y + GY * blockIdx.z);
        g_part[bid] = s;
        __threadfence();
        unsigned int old = atomicAdd(&g_count, 1u);
        s_islast = (old == NBLK - 1) ? 1 : 0;
    }
    __syncthreads();

    if (s_islast) {
        __threadfence();
        const volatile float* vp = g_part;
        double d0 = 0.0, d1 = 0.0, d2 = 0.0, d3 = 0.0;
        for (int i = tid; i < NBLK; i += 4 * NTHR) {
            d0 += (double)vp[i];
            d1 += (double)vp[i + NTHR];
            d2 += (double)vp[i + 2 * NTHR];
            d3 += (double)vp[i + 3 * NTHR];
        }
        double d = (d0 + d1) + (d2 + d3);
        #pragma unroll
        for (int o = 16; o > 0; o >>= 1)
            d += __shfl_xor_sync(0xffffffffu, d, o);
        if ((tid & 31) == 0) dsum[tid >> 5] = d;
        __syncthreads();
        if (tid == 0) {
            double t = 0.0;
            #pragma unroll
            for (int i = 0; i < 8; i++) t += dsum[i];
            out[0] = (float)(1.0 - t * (1.0 / NPIX));
            g_count = 0;   // reset for next graph replay
        }
    }
}

extern "C" void kernel_launch(void* const* d_in, const int* in_sizes, int n_in,
                              void* d_out, int out_size) {
    const float* denoised = (const float*)d_in[0];
    const float* clean    = (const float*)d_in[1];
    float* out = (float*)d_out;

    cudaFuncSetAttribute(ssim_main_kernel,
                         cudaFuncAttributeMaxDynamicSharedMemorySize, SMEM_TOT);

    dim3 grid(GX, GY, GZ);   // 16 x 16 x 96
    ssim_main_kernel<<<grid, NTHR, SMEM_TOT>>>(denoised, clean, out);
}

// round 16
// speedup vs baseline: 1.3811x; 1.1372x over previous
#include <cuda_runtime.h>
#include <cuda_fp16.h>

// SSIM loss: 1 - mean(ssim_map(clip(denoised), clip(clean)))
// Separable 11x11 Gaussian (sigma=1.5), zero padding.
// (32,3,512,512) fp32 x2 -> scalar fp32.
// 4-field basis (s=a+b, d=a-b); fp16-packed h-sums; packed f32x2 FFMA.
// This round: 6 blocks/SM via 42-reg cap (occ 60 -> 72%).

#define IMGW 512
#define IMGH 512
#define TW 32
#define TH 32
#define HALO 5
#define RAWV 42          // TH + 2*HALO
#define RAWH 42          // TW + 2*HALO
#define RS 44            // raw tile row stride (float2 units)
#define HS 33            // hsum row stride (elements)
#define NPIX 25165824.0  // 32*3*512*512
#define GX 16
#define GY 16
#define GZ 96
#define NBLK (GX*GY*GZ)  // 24576
#define NTHR 256

__device__ float g_part[NBLK];
__device__ unsigned int g_count;   // zero-init; last block resets to 0

typedef unsigned long long u64;

__device__ __forceinline__ u64 pk2(float x, float y) {
    u64 r; asm("mov.b64 %0,{%1,%2};" : "=l"(r) : "f"(x), "f"(y)); return r;
}
__device__ __forceinline__ float2 upk2(u64 v) {
    float2 f; asm("mov.b64 {%0,%1},%2;" : "=f"(f.x), "=f"(f.y) : "l"(v)); return f;
}
__device__ __forceinline__ u64 ffma2(u64 a, u64 b, u64 c) {
    u64 d; asm("fma.rn.f32x2 %0,%1,%2,%3;" : "=l"(d) : "l"(a), "l"(b), "l"(c)); return d;
}
__device__ __forceinline__ u64 fmul2(u64 a, u64 b) {
    u64 d; asm("mul.rn.f32x2 %0,%1,%2;" : "=l"(d) : "l"(a), "l"(b)); return d;
}

// symmetric weight index: W[k] = W[10-k], 6 distinct values
#define WIDX(kk) ((kk) <= 5 ? (kk) : 10 - (kk))

// dynamic smem layout (bytes):
#define OFF_SD   0
#define OFF_H    (OFF_SD + RAWV*RS*8)        // uint2[RAWV*HS]: {h2(F1,F2), h2(F3,F4)}
#define SMEM_TOT (OFF_H + RAWV*HS*8)         // 25872 B

__global__ __launch_bounds__(NTHR, 6) void ssim_main_kernel(
    const float* __restrict__ in1, const float* __restrict__ in2,
    float* __restrict__ out) {

    const float W[6] = {
        0.00102838f, 0.00759876f, 0.03600077f, 0.10936073f, 0.21300554f,
        0.26601172f
    };

    extern __shared__ char smem[];
    float2* s_sd = reinterpret_cast<float2*>(smem + OFF_SD);
    uint2*  s_h  = reinterpret_cast<uint2*>(smem + OFF_H);
    __shared__ float wsum[8];
    __shared__ int s_islast;
    __shared__ double dsum[8];

    const int tid = threadIdx.x;
    const int plane = blockIdx.z;
    const int row0 = blockIdx.y * TH;
    const int col0 = blockIdx.x * TW;
    const float* p1 = in1 + (size_t)plane * (IMGW * IMGH);
    const float* p2 = in2 + (size_t)plane * (IMGW * IMGH);

    // packed weights (6 distinct, both halves equal)
    u64 W2[6];
    #pragma unroll
    for (int i = 0; i < 6; i++) W2[i] = pk2(W[i], W[i]);

    // ---- Load + clip, transform to (s, d) = (a+b, a-b), zero halo pad ----
    for (int idx = tid; idx < RAWV * RAWH; idx += NTHR) {
        int r = idx / RAWH;
        int c = idx - r * RAWH;
        int gr = row0 - HALO + r;
        int gc = col0 - HALO + c;
        float s = 0.0f, d = 0.0f;
        if (gr >= 0 && gr < IMGH && gc >= 0 && gc < IMGW) {
            float a = p1[gr * IMGW + gc];
            float b = p2[gr * IMGW + gc];
            a = fminf(fmaxf(a, 0.0f), 1.0f);
            b = fminf(fmaxf(b, 0.0f), 1.0f);
            s = a + b;
            d = a - b;
        }
        s_sd[r * RS + c] = make_float2(s, d);
    }
    __syncthreads();

    // ---- Horizontal pass: 336 tasks (1 row x 4 output cols), strided ----
    for (int g = tid; g < RAWV * 8; g += NTHR) {
        const int r  = g >> 3;
        const int c0 = (g & 7) << 2;
        const u64* row = reinterpret_cast<const u64*>(s_sd + r * RS + c0);

        u64 am[4] = {0ull,0ull,0ull,0ull};   // (F1,F2)
        u64 aq[4] = {0ull,0ull,0ull,0ull};   // (F3,F4)

        #pragma unroll
        for (int k = 0; k < 14; k++) {
            u64 sdp = row[k];
            u64 sqp = fmul2(sdp, sdp);
            #pragma unroll
            for (int j = 0; j < 4; j++) {
                const int kk = k - j;
                if (kk >= 0 && kk < 11) {
                    am[j] = ffma2(W2[WIDX(kk)], sdp, am[j]);
                    aq[j] = ffma2(W2[WIDX(kk)], sqp, aq[j]);
                }
            }
        }
        int o = r * HS + c0;
        #pragma unroll
        for (int j = 0; j < 4; j++) {
            float2 fm = upk2(am[j]);
            float2 fq = upk2(aq[j]);
            __half2 hA = __floats2half2_rn(fm.x, fm.y);
            __half2 hB = __floats2half2_rn(fq.x, fq.y);
            uint2 pk;
            pk.x = *reinterpret_cast<unsigned int*>(&hA);
            pk.y = *reinterpret_cast<unsigned int*>(&hB);
            s_h[o + j] = pk;
        }
    }
    __syncthreads();

    // ---- Vertical pass + SSIM: 256 tasks, exactly 1 per thread ----
    float acc = 0.0f;
    {
        const int c  = tid & 31;
        const int r0 = (tid >> 5) << 2;    // 0..28
        u64 vA[4] = {0ull,0ull,0ull,0ull};
        u64 vB[4] = {0ull,0ull,0ull,0ull};

        #pragma unroll
        for (int k = 0; k < 14; k++) {
            int rr = (r0 + k) * HS + c;
            uint2 pk = s_h[rr];
            float2 fA = __half22float2(*reinterpret_cast<__half2*>(&pk.x));
            float2 fB = __half22float2(*reinterpret_cast<__half2*>(&pk.y));
            u64 hAp = pk2(fA.x, fA.y);
            u64 hBp = pk2(fB.x, fB.y);
            #pragma unroll
            for (int j = 0; j < 4; j++) {
                const int kk = k - j;
                if (kk >= 0 && kk < 11) {
                    vA[j] = ffma2(W2[WIDX(kk)], hAp, vA[j]);
                    vB[j] = ffma2(W2[WIDX(kk)], hBp, vB[j]);
                }
            }
        }
        const float C1 = 1e-4f;   // 0.01^2
        const float C2 = 9e-4f;   // 0.03^2
        #pragma unroll
        for (int j = 0; j < 4; j++) {
            // vA = (F1, F2) = (mu1+mu2, mu1-mu2); vB = (F3, F4) = (E(s^2), E(d^2))
            u64 sqv = fmul2(vA[j], vA[j]);
            float2 fs = upk2(sqv);
            float2 fB = upk2(vB[j]);
            float P = 0.5f * (fs.x - fs.y);     // 2*mu1*mu2
            float Q = 0.5f * (fs.x + fs.y);     // mu1^2 + mu2^2
            float R = 0.5f * (fB.x - fB.y);     // 2*E12
            float S = 0.5f * (fB.x + fB.y);     // E11 + E22
            float num = (P + C1) * (R - P + C2);
            float den = (Q + C1) * (S - Q + C2);
            acc += __fdividef(num, den);
        }
    }

    // ---- Block reduction -> per-block partial + last-block final reduce ----
    #pragma unroll
    for (int o = 16; o > 0; o >>= 1)
        acc += __shfl_xor_sync(0xffffffffu, acc, o);
    if ((tid & 31) == 0) wsum[tid >> 5] = acc;
    __syncthreads();
    if (tid == 0) {
        float s = 0.0f;
        #pragma unroll
        for (int i = 0; i < 8; i++) s += wsum[i];
        int bid = blockIdx.x + GX * (blockIdx.y + GY * blockIdx.z);
        g_part[bid] = s;
        __threadfence();
        unsigned int old = atomicAdd(&g_count, 1u);
        s_islast = (old == NBLK - 1) ? 1 : 0;
    }
    __syncthreads();

    if (s_islast) {
        __threadfence();
        const volatile float* vp = g_part;
        double d0 = 0.0, d1 = 0.0, d2 = 0.0, d3 = 0.0;
        for (int i = tid; i < NBLK; i += 4 * NTHR) {
            d0 += (double)vp[i];
            d1 += (double)vp[i + NTHR];
            d2 += (double)vp[i + 2 * NTHR];
            d3 += (double)vp[i + 3 * NTHR];
        }
        double d = (d0 + d1) + (d2 + d3);
        #pragma unroll
        for (int o = 16; o > 0; o >>= 1)
            d += __shfl_xor_sync(0xffffffffu, d, o);
        if ((tid & 31) == 0) dsum[tid >> 5] = d;
        __syncthreads();
        if (tid == 0) {
            double t = 0.0;
            #pragma unroll
            for (int i = 0; i < 8; i++) t += dsum[i];
            out[0] = (float)(1.0 - t * (1.0 / NPIX));
            g_count = 0;   // reset for next graph replay
        }
    }
}

extern "C" void kernel_launch(void* const* d_in, const int* in_sizes, int n_in,
                              void* d_out, int out_size) {
    const float* denoised = (const float*)d_in[0];
    const float* clean    = (const float*)d_in[1];
    float* out = (float*)d_out;

    cudaFuncSetAttribute(ssim_main_kernel,
                         cudaFuncAttributeMaxDynamicSharedMemorySize, SMEM_TOT);

    dim3 grid(GX, GY, GZ);   // 16 x 16 x 96
    ssim_main_kernel<<<grid, NTHR, SMEM_TOT>>>(denoised, clean, out);
}